// round 15
// baseline (speedup 1.0000x reference)
#include <cuda_runtime.h>
#include <cuda_fp16.h>
#include <mma.h>

using namespace nvcuda;

#define N     16384
#define C     64
#define KNN   16
#define O     256       // C*R
#define QB    64        // queries per block
#define TJ    64        // j-tile rows
#define NB    32        // points per block in ab_kernel
#define FINF  3.4e38f
#define FULLM 0xffffffffu

#define BP    72        // half pitch for B/A-stage tiles (144B rows, ldm mult of 8)
#define DP32  68        // float pitch for D32 tile (mult of 4)
#define DP16  72        // half  pitch for D16 tile (mult of 8)

// ---- dynamic smem layout ---------------------------------------------------
#define SM_BH   0                        //  9216  B_hi 64x72 half
#define SM_BL   9216                     //  9216  B_lo
#define SM_D32  18432                    // 17408  D32 64x68 float (A-hi stage in prologue)
#define SM_D16  35840                    //  9216  D16 64x72 half
#define SM_SQ   45056                    //   512  2 x 64 float
#define SM_LK   45568                    //  4096
#define SM_LI   49664                    //  4096
#define SM_TOTAL 53760

__device__ float g_sq[N];
__device__ __half g_hi[N * C];    // -2*x (hi part)
__device__ __half g_lo[N * C];    // -2*x (lo part)
__device__ __half g_qhi[N * C];   // +x (hi part)  A side
__device__ __half g_qlo[N * C];   // +x (lo part)
__device__ float g_A[N * O];
__device__ float g_B[N * O];
__device__ int   g_idx[N * KNN];

// ---------------------------------------------------------------------------
// squared norms + fp16 hi/lo splits (query side: x ; key side: -2x)
// ---------------------------------------------------------------------------
__global__ void sq_kernel(const float* __restrict__ x) {
    int row  = blockIdx.x * 8 + (threadIdx.x >> 5);
    int lane = threadIdx.x & 31;
    float s = 0.f;
    #pragma unroll
    for (int h = 0; h < 2; h++) {
        float v = x[row * C + 32 * h + lane];
        __half qh = __float2half_rn(v);
        g_qhi[row * C + 32 * h + lane] = qh;
        g_qlo[row * C + 32 * h + lane] = __float2half_rn(v - __half2float(qh));
        float v2 = -2.f * v;
        __half kh = __float2half_rn(v2);
        g_hi[row * C + 32 * h + lane] = kh;
        g_lo[row * C + 32 * h + lane] = __float2half_rn(v2 - __half2float(kh));
        s += v * v;
    }
    #pragma unroll
    for (int off = 16; off; off >>= 1)
        s += __shfl_down_sync(FULLM, s, off);
    if (lane == 0) g_sq[row] = s;
}

// ---------------------------------------------------------------------------
// A = x @ (W_top - W_bot) + b ;  B = x @ W_bot
// ---------------------------------------------------------------------------
__global__ __launch_bounds__(256) void ab_kernel(const float* __restrict__ x,
                                                 const float* __restrict__ W,
                                                 const float* __restrict__ b) {
    __shared__ float xs[NB][C + 1];
    const int o  = threadIdx.x;
    const int nb = blockIdx.x * NB;
    #pragma unroll
    for (int it = 0; it < (NB * C) / 256; it++) {
        int linear = threadIdx.x + 256 * it;
        xs[linear >> 6][linear & 63] = x[nb * C + linear];
    }
    __syncthreads();
    float accA[NB], accB[NB];
    float bb = b[o];
    #pragma unroll
    for (int i = 0; i < NB; i++) { accA[i] = bb; accB[i] = 0.f; }
    for (int c = 0; c < C; c++) {
        float wt = W[c * O + o];
        float wb = W[(c + C) * O + o];
        float wd = wt - wb;
        #pragma unroll
        for (int i = 0; i < NB; i++) {
            float xv = xs[i][c];
            accA[i] = fmaf(xv, wd, accA[i]);
            accB[i] = fmaf(xv, wb, accB[i]);
        }
    }
    #pragma unroll
    for (int i = 0; i < NB; i++) {
        g_A[(nb + i) * O + o] = accA[i];
        g_B[(nb + i) * O + o] = accB[i];
    }
}

// ---------------------------------------------------------------------------
// tensor-core knn: hi*hi in fp32-acc HMMA; cross terms hi*lo + lo*hi in
// fp16-acc HMMA (2x rate if supported). key = D32 + (float)D16 + sq_j.
// Register-prefetch pipeline + double-buffered SQ (round-13 proven structure).
// 512 threads = 16 warps; warp w: GEMM tile (mt=w>>2, nt=w&3),
// selection for queries [w*4, w*4+4).
// ---------------------------------------------------------------------------
__global__ __launch_bounds__(512, 1) void knn_kernel() {
    extern __shared__ __align__(16) char smem[];
    __half* BH  = (__half*)(smem + SM_BH);
    __half* BL  = (__half*)(smem + SM_BL);
    float*  D32 = (float*) (smem + SM_D32);
    __half* D16 = (__half*)(smem + SM_D16);
    float*  SQs = (float*) (smem + SM_SQ);
    float*  LK  = (float*) (smem + SM_LK);
    int*    LI  = (int*)   (smem + SM_LI);

    const int tid  = threadIdx.x;
    const int w    = tid >> 5;
    const int lane = tid & 31;
    const int mt   = w >> 2;
    const int nt   = w & 3;
    const int qBase = blockIdx.x * QB;
    const int t16  = lane & 15;
    const int pj   = tid >> 3;        // 0..63  prefetch row
    const int pk   = tid & 7;         // 0..7   prefetch 16B chunk

    // ---- prologue: stage query rows (qhi into D32 scratch, qlo into BH) ----
    {
        __half* AH = (__half*)D32;
        __half* AL = BH;
        const uint4* sh = (const uint4*)(g_qhi + (size_t)(qBase + pj) * C + pk * 8);
        const uint4* sl = (const uint4*)(g_qlo + (size_t)(qBase + pj) * C + pk * 8);
        *((uint4*)(AH + pj * BP + pk * 8)) = *sh;
        *((uint4*)(AL + pj * BP + pk * 8)) = *sl;
    }
    __syncthreads();

    wmma::fragment<wmma::matrix_a, 16, 16, 16, __half, wmma::row_major> a_hi[4], a_lo[4];
    {
        const __half* AH = (const __half*)D32;
        const __half* AL = BH;
        #pragma unroll
        for (int kk = 0; kk < 4; kk++) {
            wmma::load_matrix_sync(a_hi[kk], AH + (mt * 16) * BP + kk * 16, BP);
            wmma::load_matrix_sync(a_lo[kk], AL + (mt * 16) * BP + kk * 16, BP);
        }
    }

    if (lane < KNN) {
        #pragma unroll
        for (int qi = 0; qi < 4; qi++) {
            LK[(w * 4 + qi) * KNN + lane] = FINF;
            LI[(w * 4 + qi) * KNN + lane] = 0;
        }
    }
    float cm[4];
    #pragma unroll
    for (int qi = 0; qi < 4; qi++) cm[qi] = FINF;

    // ---- prefetch tile 0 into registers ------------------------------------
    uint4 pfh = *((const uint4*)(g_hi + (size_t)pj * C + pk * 8));
    uint4 pfl = *((const uint4*)(g_lo + (size_t)pj * C + pk * 8));
    float pfs = (tid < TJ) ? g_sq[tid] : 0.f;

    __syncthreads();   // a_frags loaded; BH scratch free

    // ---- main loop over j-tiles --------------------------------------------
    for (int jt = 0; jt < N; jt += TJ) {
        const int buf = (jt >> 6) & 1;        // TJ = 64
        // commit prefetched tile (BH/BL last read: GEMM(prev), barrier-separated)
        *((uint4*)(BH + pj * BP + pk * 8)) = pfh;
        *((uint4*)(BL + pj * BP + pk * 8)) = pfl;
        if (tid < TJ) SQs[buf * TJ + tid] = pfs;
        __syncthreads();

        // issue next tile's loads (in flight across GEMM + selection)
        {
            int njt = (jt + TJ < N) ? jt + TJ : 0;
            pfh = *((const uint4*)(g_hi + (size_t)(njt + pj) * C + pk * 8));
            pfl = *((const uint4*)(g_lo + (size_t)(njt + pj) * C + pk * 8));
            if (tid < TJ) pfs = g_sq[njt + tid];
        }

        // GEMM: hi*hi -> fp32 acc ; hi*lo + lo*hi -> fp16 acc
        {
            wmma::fragment<wmma::accumulator, 16, 16, 16, float>  acc32;
            wmma::fragment<wmma::accumulator, 16, 16, 16, __half> acc16;
            wmma::fill_fragment(acc32, 0.f);
            wmma::fill_fragment(acc16, __float2half(0.f));
            #pragma unroll
            for (int kk = 0; kk < 4; kk++) {
                wmma::fragment<wmma::matrix_b, 16, 16, 16, __half, wmma::col_major> b_hi, b_lo;
                wmma::load_matrix_sync(b_hi, BH + (nt * 16) * BP + kk * 16, BP);
                wmma::load_matrix_sync(b_lo, BL + (nt * 16) * BP + kk * 16, BP);
                wmma::mma_sync(acc32, a_hi[kk], b_hi, acc32);
                wmma::mma_sync(acc16, a_hi[kk], b_lo, acc16);
                wmma::mma_sync(acc16, a_lo[kk], b_hi, acc16);
            }
            wmma::store_matrix_sync(D32 + (mt * 16) * DP32 + nt * 16, acc32, DP32,
                                    wmma::mem_row_major);
            wmma::store_matrix_sync(D16 + (mt * 16) * DP16 + nt * 16, acc16, DP16,
                                    wmma::mem_row_major);
        }
        __syncthreads();

        // selection: warp w handles queries w*4..w*4+3
        #pragma unroll
        for (int qi = 0; qi < 4; qi++) {
            const int q  = w * 4 + qi;
            const int qg = qBase + q;
            float key[2];
            #pragma unroll
            for (int g = 0; g < 2; g++) {
                int jj = lane + 32 * g;
                key[g] = D32[q * DP32 + jj] + __half2float(D16[q * DP16 + jj])
                       + SQs[buf * TJ + jj];
                if (jt + jj == qg) key[g] = FINF;      // exclude self
            }
            float kmin = fminf(key[0], key[1]);
            if (__ballot_sync(FULLM, kmin < cm[qi])) {
                #pragma unroll
                for (int g = 0; g < 2; g++) {
                    unsigned bmask = __ballot_sync(FULLM, key[g] < cm[qi]);
                    while (bmask) {
                        int src = __ffs(bmask) - 1;
                        bmask &= bmask - 1;
                        float ck = __shfl_sync(FULLM, key[g], src);
                        int   cj = jt + src + 32 * g;
                        if (ck < cm[qi]) {             // re-check vs updated cm
                            float lv = (lane < KNN) ? LK[q * KNN + t16] : -FINF;
                            int   lp = t16;
                            #pragma unroll
                            for (int off = 8; off; off >>= 1) {
                                float ov = __shfl_xor_sync(FULLM, lv, off);
                                int   op = __shfl_xor_sync(FULLM, lp, off);
                                if (ov > lv || (ov == lv && op < lp)) { lv = ov; lp = op; }
                            }
                            int mp = __shfl_sync(FULLM, lp, 0);
                            if (lane == 0) { LK[q * KNN + mp] = ck; LI[q * KNN + mp] = cj; }
                            __syncwarp(FULLM);
                            float nv = (lane < KNN) ? LK[q * KNN + t16] : -FINF;
                            #pragma unroll
                            for (int off = 8; off; off >>= 1)
                                nv = fmaxf(nv, __shfl_xor_sync(FULLM, nv, off));
                            cm[qi] = __shfl_sync(FULLM, nv, 0);
                        }
                    }
                }
            }
        }
    }

    // ---- write out lists (order irrelevant: feeds max-pool) ----------------
    __syncwarp(FULLM);
    if (lane < KNN) {
        #pragma unroll
        for (int qi = 0; qi < 4; qi++)
            g_idx[(qBase + w * 4 + qi) * KNN + lane] = LI[(w * 4 + qi) * KNN + lane];
    }
}

// ---------------------------------------------------------------------------
// out[n, o] = relu(A[n,o] + max_k B[idx[n,k], o]) ; permuted store
// ---------------------------------------------------------------------------
__global__ void out_kernel(float* __restrict__ y) {
    __shared__ int idxs[KNN];
    int n = blockIdx.x;
    int o = threadIdx.x;
    if (o < KNN) idxs[o] = g_idx[n * KNN + o];
    __syncthreads();
    float m = -FINF;
    #pragma unroll
    for (int k = 0; k < KNN; k++)
        m = fmaxf(m, g_B[idxs[k] * O + o]);
    float v = fmaxf(g_A[n * O + o] + m, 0.f);
    y[(n * 4 + (o & 3)) * C + (o >> 2)] = v;
}

// ---------------------------------------------------------------------------
extern "C" void kernel_launch(void* const* d_in, const int* in_sizes, int n_in,
                              void* d_out, int out_size) {
    const float* x = (const float*)d_in[0];
    const float* W = (const float*)d_in[1];
    const float* b = (const float*)d_in[2];
    float* y = (float*)d_out;

    static int configured = 0;
    if (!configured) {
        cudaFuncSetAttribute(knn_kernel,
                             cudaFuncAttributeMaxDynamicSharedMemorySize, SM_TOTAL);
        configured = 1;
    }

    sq_kernel <<<N / 8, 256>>>(x);
    knn_kernel<<<N / QB, 512, SM_TOTAL>>>();
    ab_kernel <<<N / NB, 256>>>(x, W, b);
    out_kernel<<<N, 256>>>(y);
}